// round 16
// baseline (speedup 1.0000x reference)
#include <cuda_runtime.h>
#include <cuda_fp16.h>
#include <cstdint>

#define DIM   768
#define HEADS 12
#define HDIM  64
#define SEQ   1024
#define BATCH 8
#define ROWS  (BATCH*SEQ)   // 8192
#define NQKV  (3*DIM)       // 2304
#define LN_EPS 1e-5f

// ---------------- scratch (fp16 datapath) ----------------
__device__ __half g_xnorm[ROWS*DIM];
__device__ __half g_Q[ROWS*DIM];      // (B,H,N,D)
__device__ __half g_K[ROWS*DIM];
__device__ __half g_V[ROWS*DIM];
__device__ __half g_attn[ROWS*DIM];   // (B,N,C)
__device__ __half g_Wqkv[DIM*NQKV];   // [k][3*768] concat Q|K|V
__device__ __half g_Wo[DIM*DIM];      // [k][n]

// ---------------- helpers ----------------
__device__ __forceinline__ void cp_async16(void* smem_ptr, const void* gptr) {
    uint32_t sa = (uint32_t)__cvta_generic_to_shared(smem_ptr);
    asm volatile("cp.async.cg.shared.global [%0], [%1], 16;" :: "r"(sa), "l"(gptr));
}
#define CP_COMMIT()  asm volatile("cp.async.commit_group;")
#define CP_WAIT(n)   asm volatile("cp.async.wait_group %0;" :: "n"(n))

#define LDSM_X4(d0,d1,d2,d3,addr) \
  asm volatile("ldmatrix.sync.aligned.m8n8.x4.shared.b16 {%0,%1,%2,%3}, [%4];" \
    : "=r"(d0), "=r"(d1), "=r"(d2), "=r"(d3) : "r"(addr))
#define LDSM_X4T(d0,d1,d2,d3,addr) \
  asm volatile("ldmatrix.sync.aligned.m8n8.x4.trans.shared.b16 {%0,%1,%2,%3}, [%4];" \
    : "=r"(d0), "=r"(d1), "=r"(d2), "=r"(d3) : "r"(addr))

#define MMA_F16(c, a0,a1,a2,a3, b0,b1) \
  asm volatile("mma.sync.aligned.m16n8k16.row.col.f32.f16.f16.f32 " \
    "{%0,%1,%2,%3}, {%4,%5,%6,%7}, {%8,%9}, {%0,%1,%2,%3};" \
    : "+f"((c)[0]), "+f"((c)[1]), "+f"((c)[2]), "+f"((c)[3]) \
    : "r"(a0), "r"(a1), "r"(a2), "r"(a3), "r"(b0), "r"(b1))

// ---------------- fused prep: weight converts + LayerNorm ----------------
// blocks [0, 1728): Wqkv convert; [1728, 2304): Wo convert; [2304, 3328): LN (8 rows each)
#define PREP_WQKV_BLKS (DIM * NQKV / 1024)   // 1728
#define PREP_WO_BLKS   (DIM * DIM / 1024)    // 576
#define PREP_LN_BLKS   (ROWS / 8)            // 1024
#define PREP_BLKS      (PREP_WQKV_BLKS + PREP_WO_BLKS + PREP_LN_BLKS)

__global__ __launch_bounds__(256) void prep_kernel(
    const float* __restrict__ Wq, const float* __restrict__ Wk,
    const float* __restrict__ Wv, const float* __restrict__ Wo,
    const float* __restrict__ x, const float* __restrict__ gamma,
    const float* __restrict__ beta) {
    int blk = blockIdx.x;
    if (blk < PREP_WQKV_BLKS) {
        int idx = (blk * 256 + threadIdx.x) * 4;
        int k = idx / NQKV, ng = idx - k * NQKV;
        int which = ng / DIM, n = ng - which * DIM;
        const float* W = (which == 0) ? Wq : ((which == 1) ? Wk : Wv);
        float4 v = *(const float4*)&W[(size_t)k * DIM + n];
        __half* dst = &g_Wqkv[(size_t)k * NQKV + ng];
        *(half2*)dst       = __floats2half2_rn(v.x, v.y);
        *(half2*)(dst + 2) = __floats2half2_rn(v.z, v.w);
    } else if (blk < PREP_WQKV_BLKS + PREP_WO_BLKS) {
        int idx = ((blk - PREP_WQKV_BLKS) * 256 + threadIdx.x) * 4;
        float4 v = *(const float4*)&Wo[idx];
        __half* dst = &g_Wo[idx];
        *(half2*)dst       = __floats2half2_rn(v.x, v.y);
        *(half2*)(dst + 2) = __floats2half2_rn(v.z, v.w);
    } else {
        int row  = (blk - PREP_WQKV_BLKS - PREP_WO_BLKS) * 8 + (threadIdx.x >> 5);
        int lane = threadIdx.x & 31;
        const float* xr = x + (size_t)row * DIM;
        float4 v[6];
        float s = 0.f, sq = 0.f;
        #pragma unroll
        for (int i = 0; i < 6; i++) {
            v[i] = *(const float4*)&xr[(i * 32 + lane) * 4];
            s  += v[i].x + v[i].y + v[i].z + v[i].w;
            sq += v[i].x * v[i].x + v[i].y * v[i].y + v[i].z * v[i].z + v[i].w * v[i].w;
        }
        #pragma unroll
        for (int o = 16; o > 0; o >>= 1) {
            s  += __shfl_xor_sync(0xffffffffu, s, o);
            sq += __shfl_xor_sync(0xffffffffu, sq, o);
        }
        float mu  = s * (1.0f / DIM);
        float var = sq * (1.0f / DIM) - mu * mu;
        float inv = rsqrtf(var + LN_EPS);
        __half* orow = g_xnorm + (size_t)row * DIM;
        #pragma unroll
        for (int i = 0; i < 6; i++) {
            int c = (i * 32 + lane) * 4;
            float4 g = *(const float4*)&gamma[c];
            float4 b = *(const float4*)&beta[c];
            *(half2*)&orow[c]     = __floats2half2_rn((v[i].x - mu) * inv * g.x + b.x,
                                                      (v[i].y - mu) * inv * g.y + b.y);
            *(half2*)&orow[c + 2] = __floats2half2_rn((v[i].z - mu) * inv * g.z + b.z,
                                                      (v[i].w - mu) * inv * g.w + b.w);
        }
    }
}

// ---------------- fp16 GEMM: 128x128 tile, GBK=64, 3-stage cp.async + ldmatrix ----------------
#define GBM 128
#define GBN 128
#define GBK 64
#define NST 3
#define LDA 72     // halfs; 144B rows (conflict-free ldmatrix)
#define LDB 136    // halfs; 272B rows
#define ASZ (GBM*LDA)            // 9216 halfs
#define BSZ (GBK*LDB)            // 8704 halfs
#define STAGE_H (ASZ + BSZ)      // 17920 halfs
#define GEMM_SMEM_BYTES (NST * STAGE_H * 2)   // 107520
#define KT (DIM / GBK)           // 12

__device__ __forceinline__ void gemm_issue_stage(
    const __half* __restrict__ A, const __half* __restrict__ B, int Bld,
    int row0, int col0, int k0, __half* stage,
    int a_m, int a_k0, int b_k, int b_n0) {
    __half* As = stage;
    __half* Bs = stage + ASZ;
    #pragma unroll
    for (int c = 0; c < 4; c++)
        cp_async16(&As[a_m * LDA + a_k0 + c * 8],
                   &A[(size_t)(row0 + a_m) * DIM + k0 + a_k0 + c * 8]);
    #pragma unroll
    for (int c = 0; c < 4; c++)
        cp_async16(&Bs[b_k * LDB + b_n0 + c * 8],
                   &B[(size_t)(k0 + b_k) * Bld + col0 + b_n0 + c * 8]);
}

__device__ __forceinline__ void gemm_f16_mainloop(
    const __half* __restrict__ A, const __half* __restrict__ B, int Bld,
    int row0, int col0, float c[4][4][4], __half* dsm) {
    const int t    = threadIdx.x;
    const int lane = t & 31;
    const int warp = t >> 5;
    const int wr   = warp >> 2;
    const int wc   = warp & 3;

    const int a_m  = t >> 1;         // 0..127
    const int a_k0 = (t & 1) * 32;   // 0 or 32
    const int b_k  = t >> 2;         // 0..63
    const int b_n0 = (t & 3) * 32;   // 0..96

    const int mrow = ((lane >> 3) & 1) * 8 + (lane & 7);
    const int mcol = (lane >> 4) * 8;
    const uint32_t sbase = (uint32_t)__cvta_generic_to_shared(dsm);
    const uint32_t a_lds = sbase + (uint32_t)(((wr * 64 + mrow) * LDA + mcol) * 2);
    const uint32_t b_lds = sbase + (uint32_t)((ASZ + mrow * LDB + wc * 32 + mcol) * 2);

    #pragma unroll
    for (int s = 0; s < NST - 1; s++) {
        gemm_issue_stage(A, B, Bld, row0, col0, s * GBK, dsm + s * STAGE_H, a_m, a_k0, b_k, b_n0);
        CP_COMMIT();
    }

    for (int kt = 0; kt < KT; kt++) {
        CP_WAIT(NST - 2);
        __syncthreads();

        if (kt + NST - 1 < KT) {
            gemm_issue_stage(A, B, Bld, row0, col0, (kt + NST - 1) * GBK,
                             dsm + ((kt + NST - 1) % NST) * STAGE_H, a_m, a_k0, b_k, b_n0);
        }
        CP_COMMIT();

        const uint32_t stoff = (uint32_t)((kt % NST) * STAGE_H * 2);

        #pragma unroll
        for (int kb = 0; kb < GBK; kb += 16) {
            uint32_t af[4][4], bg[2][4];
            #pragma unroll
            for (int i = 0; i < 4; i++)
                LDSM_X4(af[i][0], af[i][1], af[i][2], af[i][3],
                        a_lds + stoff + (uint32_t)((i * 16 * LDA + kb) * 2));
            #pragma unroll
            for (int j2 = 0; j2 < 2; j2++)
                LDSM_X4T(bg[j2][0], bg[j2][1], bg[j2][2], bg[j2][3],
                         b_lds + stoff + (uint32_t)((kb * LDB + j2 * 16) * 2));
            #pragma unroll
            for (int i = 0; i < 4; i++)
                #pragma unroll
                for (int j = 0; j < 4; j++)
                    MMA_F16(c[i][j], af[i][0], af[i][1], af[i][2], af[i][3],
                            bg[j >> 1][(j & 1) * 2], bg[j >> 1][(j & 1) * 2 + 1]);
        }
    }
}

__global__ __launch_bounds__(256) void qkv_gemm_f16(
    const float* __restrict__ bq, const float* __restrict__ bk,
    const float* __restrict__ bv, const float* __restrict__ pos) {
    extern __shared__ __half dsm[];
    const int row0 = blockIdx.y * GBM;
    const int col0 = blockIdx.x * GBN;

    float c[4][4][4];
    #pragma unroll
    for (int i = 0; i < 4; i++)
        #pragma unroll
        for (int j = 0; j < 4; j++)
            #pragma unroll
            for (int q = 0; q < 4; q++) c[i][j][q] = 0.f;

    gemm_f16_mainloop(g_xnorm, g_Wqkv, NQKV, row0, col0, c, dsm);

    const int lane = threadIdx.x & 31;
    const int warp = threadIdx.x >> 5;
    const int wr = warp >> 2, wc = warp & 3;
    const int lq = lane & 3, lg = lane >> 2;

    const int which = col0 / DIM;
    const float* bias = (which == 0) ? bq : ((which == 1) ? bk : bv);
    __half* out = (which == 0) ? g_Q : ((which == 1) ? g_K : g_V);

    #pragma unroll
    for (int i = 0; i < 4; i++) {
        #pragma unroll
        for (int j = 0; j < 4; j++) {
            int cg = col0 + wc * 32 + j * 8 + 2 * lq;
            int nl = cg - which * DIM;
            float b0 = bias[nl], b1 = bias[nl + 1];
            int h = nl >> 6, d = nl & 63;
            #pragma unroll
            for (int rh = 0; rh < 2; rh++) {
                int m = row0 + wr * 64 + i * 16 + lg + rh * 8;
                float v0 = c[i][j][rh * 2 + 0] + b0;
                float v1 = c[i][j][rh * 2 + 1] + b1;
                if (which == 0) {
                    float2 p = *(const float2*)&pos[(size_t)m * DIM + nl];
                    v0 += p.x; v1 += p.y;
                }
                int bidx = m >> 10, n = m & 1023;
                *(half2*)&out[(size_t)((bidx * HEADS + h) * SEQ + n) * HDIM + d] =
                    __floats2half2_rn(v0, v1);
            }
        }
    }
}

__global__ __launch_bounds__(256) void out_gemm_f16(
    const float* __restrict__ bo, const float* __restrict__ x, float* __restrict__ out) {
    extern __shared__ __half dsm[];
    const int row0 = blockIdx.y * GBM;
    const int col0 = blockIdx.x * GBN;

    float c[4][4][4];
    #pragma unroll
    for (int i = 0; i < 4; i++)
        #pragma unroll
        for (int j = 0; j < 4; j++)
            #pragma unroll
            for (int q = 0; q < 4; q++) c[i][j][q] = 0.f;

    gemm_f16_mainloop(g_attn, g_Wo, DIM, row0, col0, c, dsm);

    const int lane = threadIdx.x & 31;
    const int warp = threadIdx.x >> 5;
    const int wr = warp >> 2, wc = warp & 3;
    const int lq = lane & 3, lg = lane >> 2;

    #pragma unroll
    for (int i = 0; i < 4; i++) {
        #pragma unroll
        for (int j = 0; j < 4; j++) {
            int cc = col0 + wc * 32 + j * 8 + 2 * lq;
            float b0 = bo[cc], b1 = bo[cc + 1];
            #pragma unroll
            for (int rh = 0; rh < 2; rh++) {
                int m = row0 + wr * 64 + i * 16 + lg + rh * 8;
                float2 xr = *(const float2*)&x[(size_t)m * DIM + cc];
                float2 r;
                r.x = c[i][j][rh * 2 + 0] + b0 + xr.x;
                r.y = c[i][j][rh * 2 + 1] + b1 + xr.y;
                *(float2*)&out[(size_t)m * DIM + cc] = r;
            }
        }
    }
}

// ---------------- FA2 attention, max-free softmax + cp.async K/V pipeline (R15) ----------------
#define LDH 72
#define QS_H   (128 * LDH)
#define KV_H   (64 * LDH)
#define STG_H  (2 * KV_H)
#define ATTN_SMEM_BYTES ((QS_H + 2 * STG_H) * 2)   // 55296 B
#define NT (SEQ / 64)
#define KEXP 0.1803368801111204f   // 0.125 / ln(2)

__global__ __launch_bounds__(256) void attn_f16_kernel() {
    extern __shared__ __align__(16) __half asm_[];
    __half* Qs = asm_;

    const int t    = threadIdx.x;
    const int lane = t & 31;
    const int warp = t >> 5;
    const int lq   = lane & 3;
    const int lg   = lane >> 2;

    const int q0 = blockIdx.x * 128;
    const int bh = blockIdx.y;
    const __half* Qg = g_Q + (size_t)bh * SEQ * HDIM;
    const __half* Kg = g_K + (size_t)bh * SEQ * HDIM;
    const __half* Vg = g_V + (size_t)bh * SEQ * HDIM;

    const int mrow = ((lane >> 3) & 1) * 8 + (lane & 7);
    const int mcol = (lane >> 4) * 8;
    const int nrow = (lane >> 4) * 8 + (lane & 7);
    const int kcol = ((lane >> 3) & 1) * 8;

    const uint32_t smem_u = (uint32_t)__cvta_generic_to_shared(asm_);
    const uint32_t qs_u = smem_u;

    const int lr  = t >> 2;
    const int lc0 = (t & 3) * 16;

    {
        __half* K0 = asm_ + QS_H;
        __half* V0 = K0 + KV_H;
        const __half* ks = Kg + (size_t)lr * HDIM + lc0;
        const __half* vs = Vg + (size_t)lr * HDIM + lc0;
        cp_async16(&K0[lr * LDH + lc0],     ks);
        cp_async16(&K0[lr * LDH + lc0 + 8], ks + 8);
        cp_async16(&V0[lr * LDH + lc0],     vs);
        cp_async16(&V0[lr * LDH + lc0 + 8], vs + 8);
        CP_COMMIT();
    }

    {
        int qr = t >> 1, qc = (t & 1) * 32;
        #pragma unroll
        for (int ii = 0; ii < 4; ii++)
            *(uint4*)&Qs[qr * LDH + qc + ii * 8] =
                *(const uint4*)&Qg[(size_t)(q0 + qr) * HDIM + qc + ii * 8];
    }
    __syncthreads();

    uint32_t aq[4][4];
    {
        uint32_t abase = qs_u + (uint32_t)(((warp * 16 + mrow) * LDH + mcol) * 2);
        #pragma unroll
        for (int kb = 0; kb < 4; kb++)
            LDSM_X4(aq[kb][0], aq[kb][1], aq[kb][2], aq[kb][3],
                    abase + (uint32_t)(kb * 16 * 2));
    }

    float l0 = 0.f, l1 = 0.f;
    float o[8][4];
    #pragma unroll
    for (int j = 0; j < 8; j++)
        #pragma unroll
        for (int q = 0; q < 4; q++) o[j][q] = 0.f;

    for (int kt = 0; kt < NT; kt++) {
        const int cur = kt & 1;
        if (kt + 1 < NT) {
            __half* Kn = asm_ + QS_H + (cur ^ 1) * STG_H;
            __half* Vn = Kn + KV_H;
            const __half* ks = Kg + (size_t)((kt + 1) * 64 + lr) * HDIM + lc0;
            const __half* vs = Vg + (size_t)((kt + 1) * 64 + lr) * HDIM + lc0;
            cp_async16(&Kn[lr * LDH + lc0],     ks);
            cp_async16(&Kn[lr * LDH + lc0 + 8], ks + 8);
            cp_async16(&Vn[lr * LDH + lc0],     vs);
            cp_async16(&Vn[lr * LDH + lc0 + 8], vs + 8);
            CP_COMMIT();
            CP_WAIT(1);
        } else {
            CP_WAIT(0);
        }
        __syncthreads();

        const uint32_t ks_u = smem_u + (uint32_t)((QS_H + cur * STG_H) * 2);
        const uint32_t vs_u = ks_u + (uint32_t)(KV_H * 2);

        float c4[8][4];
        #pragma unroll
        for (int j = 0; j < 8; j++)
            #pragma unroll
            for (int q = 0; q < 4; q++) c4[j][q] = 0.f;
        #pragma unroll
        for (int kb = 0; kb < 4; kb++) {
            #pragma unroll
            for (int j2 = 0; j2 < 4; j2++) {
                uint32_t bf0, bf1, bf2, bf3;
                LDSM_X4(bf0, bf1, bf2, bf3,
                        ks_u + (uint32_t)(((j2 * 16 + nrow) * LDH + kb * 16 + kcol) * 2));
                MMA_F16(c4[2 * j2],     aq[kb][0], aq[kb][1], aq[kb][2], aq[kb][3], bf0, bf1);
                MMA_F16(c4[2 * j2 + 1], aq[kb][0], aq[kb][1], aq[kb][2], aq[kb][3], bf2, bf3);
            }
        }

        uint32_t ap[4][4];
        #pragma unroll
        for (int kk = 0; kk < 4; kk++) {
            float e00 = exp2f(c4[2 * kk][0] * KEXP);
            float e01 = exp2f(c4[2 * kk][1] * KEXP);
            float e02 = exp2f(c4[2 * kk][2] * KEXP);
            float e03 = exp2f(c4[2 * kk][3] * KEXP);
            float e10 = exp2f(c4[2 * kk + 1][0] * KEXP);
            float e11 = exp2f(c4[2 * kk + 1][1] * KEXP);
            float e12 = exp2f(c4[2 * kk + 1][2] * KEXP);
            float e13 = exp2f(c4[2 * kk + 1][3] * KEXP);
            l0 += e00 + e01 + e10 + e11;
            l1 += e02 + e03 + e12 + e13;
            half2 h;
            h = __floats2half2_rn(e00, e01); ap[kk][0] = *(uint32_t*)&h;
            h = __floats2half2_rn(e02, e03); ap[kk][1] = *(uint32_t*)&h;
            h = __floats2half2_rn(e10, e11); ap[kk][2] = *(uint32_t*)&h;
            h = __floats2half2_rn(e12, e13); ap[kk][3] = *(uint32_t*)&h;
        }

        #pragma unroll
        for (int kk = 0; kk < 4; kk++) {
            #pragma unroll
            for (int j2 = 0; j2 < 4; j2++) {
                uint32_t bf0, bf1, bf2, bf3;
                LDSM_X4T(bf0, bf1, bf2, bf3,
                         vs_u + (uint32_t)(((kk * 16 + mrow) * LDH + j2 * 16 + mcol) * 2));
                MMA_F16(o[2 * j2],     ap[kk][0], ap[kk][1], ap[kk][2], ap[kk][3], bf0, bf1);
                MMA_F16(o[2 * j2 + 1], ap[kk][0], ap[kk][1], ap[kk][2], ap[kk][3], bf2, bf3);
            }
        }
        __syncthreads();
    }

    l0 += __shfl_xor_sync(0xffffffffu, l0, 1);
    l0 += __shfl_xor_sync(0xffffffffu, l0, 2);
    l1 += __shfl_xor_sync(0xffffffffu, l1, 1);
    l1 += __shfl_xor_sync(0xffffffffu, l1, 2);

    const int b = bh / HEADS;
    const int h = bh % HEADS;
    float inv0 = 1.0f / l0, inv1 = 1.0f / l1;
    int r0 = q0 + warp * 16 + lg;
    #pragma unroll
    for (int j = 0; j < 8; j++) {
        int d = j * 8 + 2 * lq;
        *(half2*)&g_attn[(size_t)(b * SEQ + r0) * DIM + h * HDIM + d] =
            __floats2half2_rn(o[j][0] * inv0, o[j][1] * inv0);
        *(half2*)&g_attn[(size_t)(b * SEQ + r0 + 8) * DIM + h * HDIM + d] =
            __floats2half2_rn(o[j][2] * inv1, o[j][3] * inv1);
    }
}

// ---------------- launcher ----------------
extern "C" void kernel_launch(void* const* d_in, const int* in_sizes, int n_in,
                              void* d_out, int out_size) {
    const float* x     = (const float*)d_in[0];
    const float* pos   = (const float*)d_in[1];
    const float* gamma = (const float*)d_in[2];
    const float* beta  = (const float*)d_in[3];
    const float* Wq    = (const float*)d_in[4];
    const float* bq    = (const float*)d_in[5];
    const float* Wk    = (const float*)d_in[6];
    const float* bk    = (const float*)d_in[7];
    const float* Wv    = (const float*)d_in[8];
    const float* bv    = (const float*)d_in[9];
    const float* Wo    = (const float*)d_in[10];
    const float* bo    = (const float*)d_in[11];
    float* out = (float*)d_out;

    cudaFuncSetAttribute(qkv_gemm_f16, cudaFuncAttributeMaxDynamicSharedMemorySize, GEMM_SMEM_BYTES);
    cudaFuncSetAttribute(out_gemm_f16, cudaFuncAttributeMaxDynamicSharedMemorySize, GEMM_SMEM_BYTES);
    cudaFuncSetAttribute(attn_f16_kernel, cudaFuncAttributeMaxDynamicSharedMemorySize, ATTN_SMEM_BYTES);

    prep_kernel<<<PREP_BLKS, 256>>>(Wq, Wk, Wv, Wo, x, gamma, beta);
    qkv_gemm_f16<<<dim3(NQKV / GBN, ROWS / GBM), 256, GEMM_SMEM_BYTES>>>(bq, bk, bv, pos);
    attn_f16_kernel<<<dim3(SEQ / 128, BATCH * HEADS), 256, ATTN_SMEM_BYTES>>>();
    out_gemm_f16<<<dim3(DIM / GBN, ROWS / GBM), 256, GEMM_SMEM_BYTES>>>(bo, x, out);
}

// round 17
// speedup vs baseline: 1.1065x; 1.1065x over previous
#include <cuda_runtime.h>
#include <cuda_fp16.h>
#include <cstdint>

#define DIM   768
#define HEADS 12
#define HDIM  64
#define SEQ   1024
#define BATCH 8
#define ROWS  (BATCH*SEQ)   // 8192
#define NQKV  (3*DIM)       // 2304
#define LN_EPS 1e-5f

// ---------------- scratch (fp16 datapath) ----------------
__device__ __half g_xnorm[ROWS*DIM];
__device__ __half g_Q[ROWS*DIM];      // (B,H,N,D)
__device__ __half g_K[ROWS*DIM];
__device__ __half g_V[ROWS*DIM];
__device__ __half g_attn[ROWS*DIM];   // (B,N,C)
__device__ __half g_Wqkv[DIM*NQKV];   // [k][3*768] concat Q|K|V
__device__ __half g_Wo[DIM*DIM];      // [k][n]

// ---------------- helpers ----------------
__device__ __forceinline__ void cp_async16(void* smem_ptr, const void* gptr) {
    uint32_t sa = (uint32_t)__cvta_generic_to_shared(smem_ptr);
    asm volatile("cp.async.cg.shared.global [%0], [%1], 16;" :: "r"(sa), "l"(gptr));
}
#define CP_COMMIT()  asm volatile("cp.async.commit_group;")
#define CP_WAIT(n)   asm volatile("cp.async.wait_group %0;" :: "n"(n))

#define LDSM_X4(d0,d1,d2,d3,addr) \
  asm volatile("ldmatrix.sync.aligned.m8n8.x4.shared.b16 {%0,%1,%2,%3}, [%4];" \
    : "=r"(d0), "=r"(d1), "=r"(d2), "=r"(d3) : "r"(addr))
#define LDSM_X4T(d0,d1,d2,d3,addr) \
  asm volatile("ldmatrix.sync.aligned.m8n8.x4.trans.shared.b16 {%0,%1,%2,%3}, [%4];" \
    : "=r"(d0), "=r"(d1), "=r"(d2), "=r"(d3) : "r"(addr))

#define MMA_F16(c, a0,a1,a2,a3, b0,b1) \
  asm volatile("mma.sync.aligned.m16n8k16.row.col.f32.f16.f16.f32 " \
    "{%0,%1,%2,%3}, {%4,%5,%6,%7}, {%8,%9}, {%0,%1,%2,%3};" \
    : "+f"((c)[0]), "+f"((c)[1]), "+f"((c)[2]), "+f"((c)[3]) \
    : "r"(a0), "r"(a1), "r"(a2), "r"(a3), "r"(b0), "r"(b1))

// ---------------- fused prep: weight converts + LayerNorm ----------------
#define PREP_WQKV_BLKS (DIM * NQKV / 1024)   // 1728
#define PREP_WO_BLKS   (DIM * DIM / 1024)    // 576
#define PREP_LN_BLKS   (ROWS / 8)            // 1024
#define PREP_BLKS      (PREP_WQKV_BLKS + PREP_WO_BLKS + PREP_LN_BLKS)

__global__ __launch_bounds__(256) void prep_kernel(
    const float* __restrict__ Wq, const float* __restrict__ Wk,
    const float* __restrict__ Wv, const float* __restrict__ Wo,
    const float* __restrict__ x, const float* __restrict__ gamma,
    const float* __restrict__ beta) {
    int blk = blockIdx.x;
    if (blk < PREP_WQKV_BLKS) {
        int idx = (blk * 256 + threadIdx.x) * 4;
        int k = idx / NQKV, ng = idx - k * NQKV;
        int which = ng / DIM, n = ng - which * DIM;
        const float* W = (which == 0) ? Wq : ((which == 1) ? Wk : Wv);
        float4 v = *(const float4*)&W[(size_t)k * DIM + n];
        __half* dst = &g_Wqkv[(size_t)k * NQKV + ng];
        *(half2*)dst       = __floats2half2_rn(v.x, v.y);
        *(half2*)(dst + 2) = __floats2half2_rn(v.z, v.w);
    } else if (blk < PREP_WQKV_BLKS + PREP_WO_BLKS) {
        int idx = ((blk - PREP_WQKV_BLKS) * 256 + threadIdx.x) * 4;
        float4 v = *(const float4*)&Wo[idx];
        __half* dst = &g_Wo[idx];
        *(half2*)dst       = __floats2half2_rn(v.x, v.y);
        *(half2*)(dst + 2) = __floats2half2_rn(v.z, v.w);
    } else {
        int row  = (blk - PREP_WQKV_BLKS - PREP_WO_BLKS) * 8 + (threadIdx.x >> 5);
        int lane = threadIdx.x & 31;
        const float* xr = x + (size_t)row * DIM;
        float4 v[6];
        float s = 0.f, sq = 0.f;
        #pragma unroll
        for (int i = 0; i < 6; i++) {
            v[i] = *(const float4*)&xr[(i * 32 + lane) * 4];
            s  += v[i].x + v[i].y + v[i].z + v[i].w;
            sq += v[i].x * v[i].x + v[i].y * v[i].y + v[i].z * v[i].z + v[i].w * v[i].w;
        }
        #pragma unroll
        for (int o = 16; o > 0; o >>= 1) {
            s  += __shfl_xor_sync(0xffffffffu, s, o);
            sq += __shfl_xor_sync(0xffffffffu, sq, o);
        }
        float mu  = s * (1.0f / DIM);
        float var = sq * (1.0f / DIM) - mu * mu;
        float inv = rsqrtf(var + LN_EPS);
        __half* orow = g_xnorm + (size_t)row * DIM;
        #pragma unroll
        for (int i = 0; i < 6; i++) {
            int c = (i * 32 + lane) * 4;
            float4 g = *(const float4*)&gamma[c];
            float4 b = *(const float4*)&beta[c];
            *(half2*)&orow[c]     = __floats2half2_rn((v[i].x - mu) * inv * g.x + b.x,
                                                      (v[i].y - mu) * inv * g.y + b.y);
            *(half2*)&orow[c + 2] = __floats2half2_rn((v[i].z - mu) * inv * g.z + b.z,
                                                      (v[i].w - mu) * inv * g.w + b.w);
        }
    }
}

// ---------------- fp16 GEMM: 128x128 tile, GBK=32, 4-stage cp.async + ldmatrix (R15) ----------------
#define GBM 128
#define GBN 128
#define GBK 32
#define NST 4
#define LDA 40
#define LDB 136
#define ASZ (GBM*LDA)
#define BSZ (GBK*LDB)
#define STAGE_H (ASZ + BSZ)
#define GEMM_SMEM_BYTES (NST * STAGE_H * 2)
#define KT (DIM / GBK)

__device__ __forceinline__ void gemm_issue_stage(
    const __half* __restrict__ A, const __half* __restrict__ B, int Bld,
    int row0, int col0, int k0, __half* stage,
    int a_m, int a_k0, int b_k, int b_n0) {
    __half* As = stage;
    __half* Bs = stage + ASZ;
    cp_async16(&As[a_m * LDA + a_k0],     &A[(size_t)(row0 + a_m) * DIM + k0 + a_k0]);
    cp_async16(&As[a_m * LDA + a_k0 + 8], &A[(size_t)(row0 + a_m) * DIM + k0 + a_k0 + 8]);
    cp_async16(&Bs[b_k * LDB + b_n0],     &B[(size_t)(k0 + b_k) * Bld + col0 + b_n0]);
    cp_async16(&Bs[b_k * LDB + b_n0 + 8], &B[(size_t)(k0 + b_k) * Bld + col0 + b_n0 + 8]);
}

__device__ __forceinline__ void gemm_f16_mainloop(
    const __half* __restrict__ A, const __half* __restrict__ B, int Bld,
    int row0, int col0, float c[4][4][4], __half* dsm) {
    const int t    = threadIdx.x;
    const int lane = t & 31;
    const int warp = t >> 5;
    const int wr   = warp >> 2;
    const int wc   = warp & 3;

    const int a_m  = t >> 1;
    const int a_k0 = (t & 1) * 16;
    const int b_k  = t >> 3;
    const int b_n0 = (t & 7) * 16;

    const int mrow = ((lane >> 3) & 1) * 8 + (lane & 7);
    const int mcol = (lane >> 4) * 8;
    const uint32_t sbase = (uint32_t)__cvta_generic_to_shared(dsm);
    const uint32_t a_lds = sbase + (uint32_t)(((wr * 64 + mrow) * LDA + mcol) * 2);
    const uint32_t b_lds = sbase + (uint32_t)((ASZ + mrow * LDB + wc * 32 + mcol) * 2);

    #pragma unroll
    for (int s = 0; s < NST - 1; s++) {
        gemm_issue_stage(A, B, Bld, row0, col0, s * GBK, dsm + s * STAGE_H, a_m, a_k0, b_k, b_n0);
        CP_COMMIT();
    }

    for (int kt = 0; kt < KT; kt++) {
        CP_WAIT(NST - 2);
        __syncthreads();

        if (kt + NST - 1 < KT) {
            gemm_issue_stage(A, B, Bld, row0, col0, (kt + NST - 1) * GBK,
                             dsm + ((kt + NST - 1) % NST) * STAGE_H, a_m, a_k0, b_k, b_n0);
        }
        CP_COMMIT();

        const uint32_t stoff = (uint32_t)((kt % NST) * STAGE_H * 2);

        #pragma unroll
        for (int kb = 0; kb < GBK; kb += 16) {
            uint32_t af[4][4], bg[2][4];
            #pragma unroll
            for (int i = 0; i < 4; i++)
                LDSM_X4(af[i][0], af[i][1], af[i][2], af[i][3],
                        a_lds + stoff + (uint32_t)((i * 16 * LDA + kb) * 2));
            #pragma unroll
            for (int j2 = 0; j2 < 2; j2++)
                LDSM_X4T(bg[j2][0], bg[j2][1], bg[j2][2], bg[j2][3],
                         b_lds + stoff + (uint32_t)((kb * LDB + j2 * 16) * 2));
            #pragma unroll
            for (int i = 0; i < 4; i++)
                #pragma unroll
                for (int j = 0; j < 4; j++)
                    MMA_F16(c[i][j], af[i][0], af[i][1], af[i][2], af[i][3],
                            bg[j >> 1][(j & 1) * 2], bg[j >> 1][(j & 1) * 2 + 1]);
        }
    }
}

__global__ __launch_bounds__(256) void qkv_gemm_f16(
    const float* __restrict__ bq, const float* __restrict__ bk,
    const float* __restrict__ bv, const float* __restrict__ pos) {
    extern __shared__ __half dsm[];
    const int row0 = blockIdx.y * GBM;
    const int col0 = blockIdx.x * GBN;

    float c[4][4][4];
    #pragma unroll
    for (int i = 0; i < 4; i++)
        #pragma unroll
        for (int j = 0; j < 4; j++)
            #pragma unroll
            for (int q = 0; q < 4; q++) c[i][j][q] = 0.f;

    gemm_f16_mainloop(g_xnorm, g_Wqkv, NQKV, row0, col0, c, dsm);

    const int lane = threadIdx.x & 31;
    const int warp = threadIdx.x >> 5;
    const int wr = warp >> 2, wc = warp & 3;
    const int lq = lane & 3, lg = lane >> 2;

    const int which = col0 / DIM;
    const float* bias = (which == 0) ? bq : ((which == 1) ? bk : bv);
    __half* out = (which == 0) ? g_Q : ((which == 1) ? g_K : g_V);

    #pragma unroll
    for (int i = 0; i < 4; i++) {
        #pragma unroll
        for (int j = 0; j < 4; j++) {
            int cg = col0 + wc * 32 + j * 8 + 2 * lq;
            int nl = cg - which * DIM;
            float b0 = bias[nl], b1 = bias[nl + 1];
            int h = nl >> 6, d = nl & 63;
            #pragma unroll
            for (int rh = 0; rh < 2; rh++) {
                int m = row0 + wr * 64 + i * 16 + lg + rh * 8;
                float v0 = c[i][j][rh * 2 + 0] + b0;
                float v1 = c[i][j][rh * 2 + 1] + b1;
                if (which == 0) {
                    float2 p = *(const float2*)&pos[(size_t)m * DIM + nl];
                    v0 += p.x; v1 += p.y;
                }
                int bidx = m >> 10, n = m & 1023;
                *(half2*)&out[(size_t)((bidx * HEADS + h) * SEQ + n) * HDIM + d] =
                    __floats2half2_rn(v0, v1);
            }
        }
    }
}

__global__ __launch_bounds__(256) void out_gemm_f16(
    const float* __restrict__ bo, const float* __restrict__ x, float* __restrict__ out) {
    extern __shared__ __half dsm[];
    const int row0 = blockIdx.y * GBM;
    const int col0 = blockIdx.x * GBN;

    float c[4][4][4];
    #pragma unroll
    for (int i = 0; i < 4; i++)
        #pragma unroll
        for (int j = 0; j < 4; j++)
            #pragma unroll
            for (int q = 0; q < 4; q++) c[i][j][q] = 0.f;

    gemm_f16_mainloop(g_attn, g_Wo, DIM, row0, col0, c, dsm);

    const int lane = threadIdx.x & 31;
    const int warp = threadIdx.x >> 5;
    const int wr = warp >> 2, wc = warp & 3;
    const int lq = lane & 3, lg = lane >> 2;

    #pragma unroll
    for (int i = 0; i < 4; i++) {
        #pragma unroll
        for (int j = 0; j < 4; j++) {
            int cc = col0 + wc * 32 + j * 8 + 2 * lq;
            float b0 = bo[cc], b1 = bo[cc + 1];
            #pragma unroll
            for (int rh = 0; rh < 2; rh++) {
                int m = row0 + wr * 64 + i * 16 + lg + rh * 8;
                float2 xr = *(const float2*)&x[(size_t)m * DIM + cc];
                float2 r;
                r.x = c[i][j][rh * 2 + 0] + b0 + xr.x;
                r.y = c[i][j][rh * 2 + 1] + b1 + xr.y;
                *(float2*)&out[(size_t)m * DIM + cc] = r;
            }
        }
    }
}

// ---------------- FA2 attention, max-free softmax + cp.async K/V pipeline (R15) ----------------
#define LDH 72
#define QS_H   (128 * LDH)
#define KV_H   (64 * LDH)
#define STG_H  (2 * KV_H)
#define ATTN_SMEM_BYTES ((QS_H + 2 * STG_H) * 2)   // 55296 B
#define NT (SEQ / 64)
#define KEXP 0.1803368801111204f   // 0.125 / ln(2)

__global__ __launch_bounds__(256) void attn_f16_kernel() {
    extern __shared__ __align__(16) __half asm_[];
    __half* Qs = asm_;

    const int t    = threadIdx.x;
    const int lane = t & 31;
    const int warp = t >> 5;
    const int lq   = lane & 3;
    const int lg   = lane >> 2;

    const int q0 = blockIdx.x * 128;
    const int bh = blockIdx.y;
    const __half* Qg = g_Q + (size_t)bh * SEQ * HDIM;
    const __half* Kg = g_K + (size_t)bh * SEQ * HDIM;
    const __half* Vg = g_V + (size_t)bh * SEQ * HDIM;

    const int mrow = ((lane >> 3) & 1) * 8 + (lane & 7);
    const int mcol = (lane >> 4) * 8;
    const int nrow = (lane >> 4) * 8 + (lane & 7);
    const int kcol = ((lane >> 3) & 1) * 8;

    const uint32_t smem_u = (uint32_t)__cvta_generic_to_shared(asm_);
    const uint32_t qs_u = smem_u;

    const int lr  = t >> 2;
    const int lc0 = (t & 3) * 16;

    {
        __half* K0 = asm_ + QS_H;
        __half* V0 = K0 + KV_H;
        const __half* ks = Kg + (size_t)lr * HDIM + lc0;
        const __half* vs = Vg + (size_t)lr * HDIM + lc0;
        cp_async16(&K0[lr * LDH + lc0],     ks);
        cp_async16(&K0[lr * LDH + lc0 + 8], ks + 8);
        cp_async16(&V0[lr * LDH + lc0],     vs);
        cp_async16(&V0[lr * LDH + lc0 + 8], vs + 8);
        CP_COMMIT();
    }

    {
        int qr = t >> 1, qc = (t & 1) * 32;
        #pragma unroll
        for (int ii = 0; ii < 4; ii++)
            *(uint4*)&Qs[qr * LDH + qc + ii * 8] =
                *(const uint4*)&Qg[(size_t)(q0 + qr) * HDIM + qc + ii * 8];
    }
    __syncthreads();

    uint32_t aq[4][4];
    {
        uint32_t abase = qs_u + (uint32_t)(((warp * 16 + mrow) * LDH + mcol) * 2);
        #pragma unroll
        for (int kb = 0; kb < 4; kb++)
            LDSM_X4(aq[kb][0], aq[kb][1], aq[kb][2], aq[kb][3],
                    abase + (uint32_t)(kb * 16 * 2));
    }

    float l0 = 0.f, l1 = 0.f;
    float o[8][4];
    #pragma unroll
    for (int j = 0; j < 8; j++)
        #pragma unroll
        for (int q = 0; q < 4; q++) o[j][q] = 0.f;

    for (int kt = 0; kt < NT; kt++) {
        const int cur = kt & 1;
        if (kt + 1 < NT) {
            __half* Kn = asm_ + QS_H + (cur ^ 1) * STG_H;
            __half* Vn = Kn + KV_H;
            const __half* ks = Kg + (size_t)((kt + 1) * 64 + lr) * HDIM + lc0;
            const __half* vs = Vg + (size_t)((kt + 1) * 64 + lr) * HDIM + lc0;
            cp_async16(&Kn[lr * LDH + lc0],     ks);
            cp_async16(&Kn[lr * LDH + lc0 + 8], ks + 8);
            cp_async16(&Vn[lr * LDH + lc0],     vs);
            cp_async16(&Vn[lr * LDH + lc0 + 8], vs + 8);
            CP_COMMIT();
            CP_WAIT(1);
        } else {
            CP_WAIT(0);
        }
        __syncthreads();

        const uint32_t ks_u = smem_u + (uint32_t)((QS_H + cur * STG_H) * 2);
        const uint32_t vs_u = ks_u + (uint32_t)(KV_H * 2);

        float c4[8][4];
        #pragma unroll
        for (int j = 0; j < 8; j++)
            #pragma unroll
            for (int q = 0; q < 4; q++) c4[j][q] = 0.f;
        #pragma unroll
        for (int kb = 0; kb < 4; kb++) {
            #pragma unroll
            for (int j2 = 0; j2 < 4; j2++) {
                uint32_t bf0, bf1, bf2, bf3;
                LDSM_X4(bf0, bf1, bf2, bf3,
                        ks_u + (uint32_t)(((j2 * 16 + nrow) * LDH + kb * 16 + kcol) * 2));
                MMA_F16(c4[2 * j2],     aq[kb][0], aq[kb][1], aq[kb][2], aq[kb][3], bf0, bf1);
                MMA_F16(c4[2 * j2 + 1], aq[kb][0], aq[kb][1], aq[kb][2], aq[kb][3], bf2, bf3);
            }
        }

        uint32_t ap[4][4];
        #pragma unroll
        for (int kk = 0; kk < 4; kk++) {
            float e00 = exp2f(c4[2 * kk][0] * KEXP);
            float e01 = exp2f(c4[2 * kk][1] * KEXP);
            float e02 = exp2f(c4[2 * kk][2] * KEXP);
            float e03 = exp2f(c4[2 * kk][3] * KEXP);
            float e10 = exp2f(c4[2 * kk + 1][0] * KEXP);
            float e11 = exp2f(c4[2 * kk + 1][1] * KEXP);
            float e12 = exp2f(c4[2 * kk + 1][2] * KEXP);
            float e13 = exp2f(c4[2 * kk + 1][3] * KEXP);
            l0 += e00 + e01 + e10 + e11;
            l1 += e02 + e03 + e12 + e13;
            half2 h;
            h = __floats2half2_rn(e00, e01); ap[kk][0] = *(uint32_t*)&h;
            h = __floats2half2_rn(e02, e03); ap[kk][1] = *(uint32_t*)&h;
            h = __floats2half2_rn(e10, e11); ap[kk][2] = *(uint32_t*)&h;
            h = __floats2half2_rn(e12, e13); ap[kk][3] = *(uint32_t*)&h;
        }

        #pragma unroll
        for (int kk = 0; kk < 4; kk++) {
            #pragma unroll
            for (int j2 = 0; j2 < 4; j2++) {
                uint32_t bf0, bf1, bf2, bf3;
                LDSM_X4T(bf0, bf1, bf2, bf3,
                         vs_u + (uint32_t)(((kk * 16 + mrow) * LDH + j2 * 16 + mcol) * 2));
                MMA_F16(o[2 * j2],     ap[kk][0], ap[kk][1], ap[kk][2], ap[kk][3], bf0, bf1);
                MMA_F16(o[2 * j2 + 1], ap[kk][0], ap[kk][1], ap[kk][2], ap[kk][3], bf2, bf3);
            }
        }
        __syncthreads();
    }

    l0 += __shfl_xor_sync(0xffffffffu, l0, 1);
    l0 += __shfl_xor_sync(0xffffffffu, l0, 2);
    l1 += __shfl_xor_sync(0xffffffffu, l1, 1);
    l1 += __shfl_xor_sync(0xffffffffu, l1, 2);

    const int b = bh / HEADS;
    const int h = bh % HEADS;
    float inv0 = 1.0f / l0, inv1 = 1.0f / l1;
    int r0 = q0 + warp * 16 + lg;
    #pragma unroll
    for (int j = 0; j < 8; j++) {
        int d = j * 8 + 2 * lq;
        *(half2*)&g_attn[(size_t)(b * SEQ + r0) * DIM + h * HDIM + d] =
            __floats2half2_rn(o[j][0] * inv0, o[j][1] * inv0);
        *(half2*)&g_attn[(size_t)(b * SEQ + r0 + 8) * DIM + h * HDIM + d] =
            __floats2half2_rn(o[j][2] * inv1, o[j][3] * inv1);
    }
}

// ---------------- launcher ----------------
extern "C" void kernel_launch(void* const* d_in, const int* in_sizes, int n_in,
                              void* d_out, int out_size) {
    const float* x     = (const float*)d_in[0];
    const float* pos   = (const float*)d_in[1];
    const float* gamma = (const float*)d_in[2];
    const float* beta  = (const float*)d_in[3];
    const float* Wq    = (const float*)d_in[4];
    const float* bq    = (const float*)d_in[5];
    const float* Wk    = (const float*)d_in[6];
    const float* bk    = (const float*)d_in[7];
    const float* Wv    = (const float*)d_in[8];
    const float* bv    = (const float*)d_in[9];
    const float* Wo    = (const float*)d_in[10];
    const float* bo    = (const float*)d_in[11];
    float* out = (float*)d_out;

    cudaFuncSetAttribute(qkv_gemm_f16, cudaFuncAttributeMaxDynamicSharedMemorySize, GEMM_SMEM_BYTES);
    cudaFuncSetAttribute(out_gemm_f16, cudaFuncAttributeMaxDynamicSharedMemorySize, GEMM_SMEM_BYTES);
    cudaFuncSetAttribute(attn_f16_kernel, cudaFuncAttributeMaxDynamicSharedMemorySize, ATTN_SMEM_BYTES);

    prep_kernel<<<PREP_BLKS, 256>>>(Wq, Wk, Wv, Wo, x, gamma, beta);
    qkv_gemm_f16<<<dim3(NQKV / GBN, ROWS / GBM), 256, GEMM_SMEM_BYTES>>>(bq, bk, bv, pos);
    attn_f16_kernel<<<dim3(SEQ / 128, BATCH * HEADS), 256, ATTN_SMEM_BYTES>>>();
    out_gemm_f16<<<dim3(DIM / GBN, ROWS / GBM), 256, GEMM_SMEM_BYTES>>>(bo, x, out);
}